// round 14
// baseline (speedup 1.0000x reference)
#include <cuda_runtime.h>
#include <cuda_bf16.h>
#include <math.h>
#include <stdint.h>

// Problem shapes (fixed by the dataset)
#define BQ   2
#define NN   50000
#define DD   128
#define ROWS (BQ * NN)          // 100000 rows of [D]
#define EMAX 2000000
#define NCHUNK ((NN + 255) / 256)   // 196

// Scratch
__device__ float g_m[(size_t)ROWS * DD];   // m = H@W  (51.2 MB)
__device__ int   g_cnt[NN];                // per-dst edge counts
__device__ int   g_off[NN + 1];            // CSR row offsets
__device__ int   g_cur[NN];                // fill cursors
__device__ int   g_esrc[EMAX];             // src ids grouped by dst
__device__ int   g_chunksum[256];          // scan partials
// Pre-packed B fragments for mma.sync m16n8k16 (row.col), hi/lo split of W.
__device__ uint2 g_bhi[8][16][32];
__device__ uint2 g_blo[8][16][32];

// ---------------------------------------------------------------------------
__device__ __forceinline__ int load_idx(const void* p, int e, int is64) {
    return is64 ? (int)((const long long*)p)[e] : ((const int*)p)[e];
}
__device__ __forceinline__ int detect_is64(const unsigned int* raw) {
    unsigned int acc = 0;
#pragma unroll
    for (int k = 0; k < 16; k++) acc |= raw[2 * k + 1];
    return (acc == 0u) ? 1 : 0;
}
__device__ __forceinline__ uint32_t pack_bf2(__nv_bfloat16 a, __nv_bfloat16 b) {
    __nv_bfloat162 p(a, b);
    return *(uint32_t*)&p;
}

// ---------------------------------------------------------------------------
// Kernel 0a (main stream): zero per-dst counters.
// ---------------------------------------------------------------------------
__global__ __launch_bounds__(256) void zero_kernel()
{
    const int i = blockIdx.x * 256 + threadIdx.x;
    if (i < NN) g_cnt[i] = 0;
}

// ---------------------------------------------------------------------------
// Kernel 0b (side stream): pack W into hi/lo mma B-fragments.
// ---------------------------------------------------------------------------
__global__ __launch_bounds__(256) void wprep_kernel(const float* __restrict__ W)
{
    const int idx = blockIdx.x * 256 + threadIdx.x;
    if (idx < 8 * 16 * 32) {
        const int lane = idx & 31;
        const int nb   = (idx >> 5) & 15;
        const int kc   = idx >> 9;
        const int g = lane >> 2, t = lane & 3;
        const int n  = nb * 8 + g;
        const int k0 = kc * 16 + 2 * t;
        const float w0 = W[(k0    ) * DD + n];
        const float w1 = W[(k0 + 1) * DD + n];
        const float w2 = W[(k0 + 8) * DD + n];
        const float w3 = W[(k0 + 9) * DD + n];
        const __nv_bfloat16 h0 = __float2bfloat16(w0), h1 = __float2bfloat16(w1);
        const __nv_bfloat16 h2 = __float2bfloat16(w2), h3 = __float2bfloat16(w3);
        const __nv_bfloat16 l0 = __float2bfloat16(w0 - __bfloat162float(h0));
        const __nv_bfloat16 l1 = __float2bfloat16(w1 - __bfloat162float(h1));
        const __nv_bfloat16 l2 = __float2bfloat16(w2 - __bfloat162float(h2));
        const __nv_bfloat16 l3 = __float2bfloat16(w3 - __bfloat162float(h3));
        g_bhi[kc][nb][lane] = make_uint2(pack_bf2(h0, h1), pack_bf2(h2, h3));
        g_blo[kc][nb][lane] = make_uint2(pack_bf2(l0, l1), pack_bf2(l2, l3));
    }
}

// ---------------------------------------------------------------------------
// Kernel 1: histogram of dst (self-detecting index dtype)
// ---------------------------------------------------------------------------
__global__ __launch_bounds__(256) void hist_kernel(const void* __restrict__ dst, int E)
{
    __shared__ int s_is64;
    if (threadIdx.x == 0) s_is64 = detect_is64((const unsigned int*)dst);
    __syncthreads();
    const int e = blockIdx.x * 256 + threadIdx.x;
    if (e >= E) return;
    const int d = load_idx(dst, e, s_is64);
    if ((unsigned)d < (unsigned)NN) atomicAdd(&g_cnt[d], 1);
}

// ---------------------------------------------------------------------------
// Kernel 2: scan1 (per-256-chunk sums)
// ---------------------------------------------------------------------------
__global__ __launch_bounds__(256) void scan1_kernel()
{
    __shared__ int sh[256];
    const int i = blockIdx.x * 256 + threadIdx.x;
    int v = (i < NN) ? g_cnt[i] : 0;
    sh[threadIdx.x] = v;
    __syncthreads();
#pragma unroll
    for (int s = 128; s > 0; s >>= 1) {
        if (threadIdx.x < s) sh[threadIdx.x] += sh[threadIdx.x + s];
        __syncthreads();
    }
    if (threadIdx.x == 0) g_chunksum[blockIdx.x] = sh[0];
}

// ---------------------------------------------------------------------------
// Kernel 3: m = H @ W via mma.sync bf16 hi/lo split (3 terms).
// Processes rows [rowBase0, rowLimit); one 128-row tile per block.
// ---------------------------------------------------------------------------
#define ASTRIDE 72   // 64 + 8 pad (bf16 elems per smem row)

__device__ __forceinline__ void mma16816(float* c, const uint32_t* a, uint2 b) {
    asm volatile(
        "mma.sync.aligned.m16n8k16.row.col.f32.bf16.bf16.f32 "
        "{%0,%1,%2,%3}, {%4,%5,%6,%7}, {%8,%9}, {%0,%1,%2,%3};"
        : "+f"(c[0]), "+f"(c[1]), "+f"(c[2]), "+f"(c[3])
        : "r"(a[0]), "r"(a[1]), "r"(a[2]), "r"(a[3]), "r"(b.x), "r"(b.y));
}
__device__ __forceinline__ void ldmat4(uint32_t* f, uint32_t addr) {
    asm volatile("ldmatrix.sync.aligned.m8n8.x4.shared.b16 {%0,%1,%2,%3}, [%4];"
        : "=r"(f[0]), "=r"(f[1]), "=r"(f[2]), "=r"(f[3]) : "r"(addr));
}

__global__ __launch_bounds__(256, 2) void gemm_mma_kernel(
    const float* __restrict__ Hm, int rowBase0, int rowLimit)
{
    __shared__ __align__(16) __nv_bfloat16 Ahi[128][ASTRIDE];
    __shared__ __align__(16) __nv_bfloat16 Alo[128][ASTRIDE];

    const int tid = threadIdx.x;
    const int wid = tid >> 5, lane = tid & 31;
    const int wm = wid >> 1, wn = wid & 1;          // warp grid 4x2
    const int g = lane >> 2, t = lane & 3;
    const int rowBase = rowBase0 + blockIdx.x * 128;

    float acc[2][8][4];
#pragma unroll
    for (int mb = 0; mb < 2; mb++)
#pragma unroll
        for (int j = 0; j < 8; j++)
#pragma unroll
            for (int c = 0; c < 4; c++) acc[mb][j][c] = 0.f;

    const uint32_t ahi_base = (uint32_t)__cvta_generic_to_shared(&Ahi[0][0]);
    const uint32_t alo_base = (uint32_t)__cvta_generic_to_shared(&Alo[0][0]);

    const int sub = lane >> 3, rr = lane & 7;
    const int lm_row_off = (sub & 1) * 8 + rr;      // 0..15
    const int lm_col_off = (sub >> 1) * 8;          // 0 or 8

    for (int kh = 0; kh < 2; kh++) {
        // Load H half-tile 128x64 fp32, convert to bf16 hi/lo in smem
#pragma unroll
        for (int q = 0; q < 8; q++) {
            const int idx = q * 256 + tid;          // 0..2047 float4 slots
            const int r  = idx >> 4;                // 16 float4 per row
            const int c4 = idx & 15;
            const int grow = rowBase + r;
            float4 v = make_float4(0.f, 0.f, 0.f, 0.f);
            if (grow < rowLimit)
                v = *(const float4*)(Hm + (size_t)grow * DD + kh * 64 + c4 * 4);
            const __nv_bfloat16 h0 = __float2bfloat16(v.x), h1 = __float2bfloat16(v.y);
            const __nv_bfloat16 h2 = __float2bfloat16(v.z), h3 = __float2bfloat16(v.w);
            const __nv_bfloat16 l0 = __float2bfloat16(v.x - __bfloat162float(h0));
            const __nv_bfloat16 l1 = __float2bfloat16(v.y - __bfloat162float(h1));
            const __nv_bfloat16 l2 = __float2bfloat16(v.z - __bfloat162float(h2));
            const __nv_bfloat16 l3 = __float2bfloat16(v.w - __bfloat162float(h3));
            *(uint2*)&Ahi[r][c4 * 4] = make_uint2(pack_bf2(h0, h1), pack_bf2(h2, h3));
            *(uint2*)&Alo[r][c4 * 4] = make_uint2(pack_bf2(l0, l1), pack_bf2(l2, l3));
        }
        __syncthreads();

#pragma unroll
        for (int kc = 0; kc < 4; kc++) {
            uint32_t ah[2][4], al[2][4];
#pragma unroll
            for (int mb = 0; mb < 2; mb++) {
                const int row = wm * 32 + mb * 16 + lm_row_off;
                const int col = kc * 16 + lm_col_off;
                const uint32_t boff = (uint32_t)(row * ASTRIDE + col) * 2u;
                ldmat4(ah[mb], ahi_base + boff);
                ldmat4(al[mb], alo_base + boff);
            }
            const int kcg = kh * 4 + kc;
#pragma unroll
            for (int j = 0; j < 8; j++) {
                const int nb = wn * 8 + j;
                const uint2 bh = g_bhi[kcg][nb][lane];
                const uint2 bl = g_blo[kcg][nb][lane];
#pragma unroll
                for (int mb = 0; mb < 2; mb++) {
                    mma16816(acc[mb][j], ah[mb], bh);
                    mma16816(acc[mb][j], ah[mb], bl);
                    mma16816(acc[mb][j], al[mb], bh);
                }
            }
        }
        __syncthreads();
    }

    // Epilogue: write D fragments
#pragma unroll
    for (int mb = 0; mb < 2; mb++) {
        const int row0 = rowBase + wm * 32 + mb * 16 + g;
        const int row1 = row0 + 8;
#pragma unroll
        for (int j = 0; j < 8; j++) {
            const int col = wn * 64 + j * 8 + 2 * t;
            if (row0 < rowLimit)
                *(float2*)(g_m + (size_t)row0 * DD + col) =
                    make_float2(acc[mb][j][0], acc[mb][j][1]);
            if (row1 < rowLimit)
                *(float2*)(g_m + (size_t)row1 * DD + col) =
                    make_float2(acc[mb][j][2], acc[mb][j][3]);
        }
    }
}

// ---------------------------------------------------------------------------
// Kernel 4: scan2 (exclusive scan of chunk sums)
// ---------------------------------------------------------------------------
__global__ __launch_bounds__(256) void scan2_kernel()
{
    __shared__ int sh[256];
    const int t = threadIdx.x;
    int v = (t < NCHUNK) ? g_chunksum[t] : 0;
    sh[t] = v;
    __syncthreads();
#pragma unroll
    for (int o = 1; o < 256; o <<= 1) {
        int add = (t >= o) ? sh[t - o] : 0;
        __syncthreads();
        sh[t] += add;
        __syncthreads();
    }
    if (t < NCHUNK) g_chunksum[t] = sh[t] - v;   // exclusive
}

// ---------------------------------------------------------------------------
// Kernel 5: scan3 (per-element offsets)
// ---------------------------------------------------------------------------
__global__ __launch_bounds__(256) void scan3_kernel()
{
    __shared__ int sh[256];
    const int t = threadIdx.x;
    const int i = blockIdx.x * 256 + t;
    int v = (i < NN) ? g_cnt[i] : 0;
    sh[t] = v;
    __syncthreads();
#pragma unroll
    for (int o = 1; o < 256; o <<= 1) {
        int add = (t >= o) ? sh[t - o] : 0;
        __syncthreads();
        sh[t] += add;
        __syncthreads();
    }
    if (i < NN) {
        const int off = g_chunksum[blockIdx.x] + sh[t] - v;   // exclusive
        g_off[i] = off;
        g_cur[i] = off;
        if (i == NN - 1) g_off[NN] = off + v;
    }
}

// ---------------------------------------------------------------------------
// Kernel 6: fill CSR (src grouped by dst)
// ---------------------------------------------------------------------------
__global__ __launch_bounds__(256) void fill_kernel(
    const void* __restrict__ src, const void* __restrict__ dst, int E)
{
    __shared__ int s_is64;
    if (threadIdx.x == 0) s_is64 = detect_is64((const unsigned int*)dst);
    __syncthreads();
    const int e = blockIdx.x * 256 + threadIdx.x;
    if (e >= E) return;
    const int d = load_idx(dst, e, s_is64);
    const int s = load_idx(src, e, s_is64);
    if ((unsigned)d >= (unsigned)NN || (unsigned)s >= (unsigned)NN) return;
    const int pos = atomicAdd(&g_cur[d], 1);
    if (pos < EMAX) g_esrc[pos] = s;
}

// ---------------------------------------------------------------------------
// Kernel 7: fused gather-accumulate + residual + GELU + LayerNorm, one batch.
// ---------------------------------------------------------------------------
__device__ __forceinline__ float gelu_exact(float x) {
    return 0.5f * x * (1.0f + erff(x * 0.70710678118654752f));
}

__global__ __launch_bounds__(256) void agg_ln_kernel(
    const float* __restrict__ Hm, const float* __restrict__ gamma,
    const float* __restrict__ beta, float* __restrict__ out, int b)
{
    const int row = blockIdx.x * 8 + (threadIdx.x >> 5);
    if (row >= NN) return;
    const int lane = threadIdx.x & 31;

    const int beg = g_off[row];
    const int end = g_off[row + 1];

    float4 a0 = make_float4(0.f, 0.f, 0.f, 0.f);
    float4 a1 = make_float4(0.f, 0.f, 0.f, 0.f);

    const float4* mb = (const float4*)(g_m + (size_t)b * NN * DD);
    int i = beg;
    for (; i + 1 < end; i += 2) {
        const int s0 = g_esrc[i];
        const int s1 = g_esrc[i + 1];
        const float4 v0 = mb[(size_t)s0 * 32 + lane];
        const float4 v1 = mb[(size_t)s1 * 32 + lane];
        a0.x += v0.x; a0.y += v0.y; a0.z += v0.z; a0.w += v0.w;
        a1.x += v1.x; a1.y += v1.y; a1.z += v1.z; a1.w += v1.w;
    }
    if (i < end) {
        const int s0 = g_esrc[i];
        const float4 v0 = mb[(size_t)s0 * 32 + lane];
        a0.x += v0.x; a0.y += v0.y; a0.z += v0.z; a0.w += v0.w;
    }
    a0.x += a1.x; a0.y += a1.y; a0.z += a1.z; a0.w += a1.w;

    const size_t rq = (size_t)(b * NN + row) * 32 + lane;
    const float4 h = ((const float4*)Hm)[rq];

    float4 x;
    x.x = h.x + gelu_exact(a0.x);
    x.y = h.y + gelu_exact(a0.y);
    x.z = h.z + gelu_exact(a0.z);
    x.w = h.w + gelu_exact(a0.w);

    float s  = x.x + x.y + x.z + x.w;
    float ss = fmaf(x.x, x.x, fmaf(x.y, x.y, fmaf(x.z, x.z, x.w * x.w)));
#pragma unroll
    for (int o = 16; o > 0; o >>= 1) {
        s  += __shfl_xor_sync(0xFFFFFFFFu, s,  o);
        ss += __shfl_xor_sync(0xFFFFFFFFu, ss, o);
    }
    const float mean = s * (1.0f / 128.0f);
    const float var  = ss * (1.0f / 128.0f) - mean * mean;
    const float rstd = rsqrtf(var + 1e-5f);

    const float4 g  = ((const float4*)gamma)[lane];
    const float4 bt = ((const float4*)beta)[lane];

    float4 o4;
    o4.x = (x.x - mean) * rstd * g.x + bt.x;
    o4.y = (x.y - mean) * rstd * g.y + bt.y;
    o4.z = (x.z - mean) * rstd * g.z + bt.z;
    o4.w = (x.w - mean) * rstd * g.w + bt.w;

    ((float4*)out)[rq] = o4;
}

// ---------------------------------------------------------------------------
extern "C" void kernel_launch(void* const* d_in, const int* in_sizes, int n_in,
                              void* d_out, int out_size)
{
    const float* H     = (const float*)d_in[0];
    const void*  src   = d_in[1];
    const void*  dst   = d_in[2];
    const float* W     = (const float*)d_in[3];
    const float* gamma = (const float*)d_in[4];
    const float* beta  = (const float*)d_in[5];
    const int E = in_sizes[1];
    const int eb = (E + 255) / 256;
    const int gemm_blocks = (NN + 127) / 128;   // per-batch

    // Side stream + events, created once on the first (uncaptured) call.
    static cudaStream_t s_side = 0;
    static cudaEvent_t  ev_fork = 0, ev_g0 = 0, ev_g1 = 0;
    if (s_side == 0) {
        cudaStreamCreateWithFlags(&s_side, cudaStreamNonBlocking);
        cudaEventCreateWithFlags(&ev_fork, cudaEventDisableTiming);
        cudaEventCreateWithFlags(&ev_g0, cudaEventDisableTiming);
        cudaEventCreateWithFlags(&ev_g1, cudaEventDisableTiming);
    }

    // Fork side stream at the very start (capture-legal rooting).
    cudaEventRecord(ev_fork, 0);
    cudaStreamWaitEvent(s_side, ev_fork, 0);

    // Side stream: W-prep -> gemm(batch0) -> ev_g0 -> gemm(batch1) -> ev_g1
    wprep_kernel<<<(4096 + 255) / 256, 256, 0, s_side>>>(W);
    gemm_mma_kernel<<<gemm_blocks, 256, 0, s_side>>>(H, 0, NN);
    cudaEventRecord(ev_g0, s_side);
    gemm_mma_kernel<<<gemm_blocks, 256, 0, s_side>>>(H, NN, 2 * NN);
    cudaEventRecord(ev_g1, s_side);

    // Main stream: CSR build
    zero_kernel<<<(NN + 255) / 256, 256>>>();
    hist_kernel<<<eb, 256>>>(dst, E);
    scan1_kernel<<<NCHUNK, 256>>>();
    scan2_kernel<<<1, 256>>>();
    scan3_kernel<<<NCHUNK, 256>>>();
    fill_kernel<<<eb, 256>>>(src, dst, E);

    // agg_ln(batch0) overlaps gemm(batch1)
    cudaStreamWaitEvent(0, ev_g0, 0);
    agg_ln_kernel<<<(NN + 7) / 8, 256>>>(H, gamma, beta, (float*)d_out, 0);
    cudaStreamWaitEvent(0, ev_g1, 0);
    agg_ln_kernel<<<(NN + 7) / 8, 256>>>(H, gamma, beta, (float*)d_out, 1);
}

// round 15
// speedup vs baseline: 1.0982x; 1.0982x over previous
#include <cuda_runtime.h>
#include <cuda_bf16.h>
#include <cuda_fp16.h>
#include <math.h>
#include <stdint.h>

// Problem shapes (fixed by the dataset)
#define BQ   2
#define NN   50000
#define DD   128
#define ROWS (BQ * NN)          // 100000 rows of [D]
#define EMAX 2000000
#define NCHUNK ((NN + 255) / 256)   // 196

// Scratch
__device__ __half g_m[(size_t)ROWS * DD];  // m = H@W in fp16 (25.6 MB)
__device__ int   g_cnt[NN];                // per-dst edge counts
__device__ int   g_off[NN + 1];            // CSR row offsets
__device__ int   g_cur[NN];                // fill cursors
__device__ int   g_esrc[EMAX];             // src ids grouped by dst
__device__ int   g_chunksum[256];          // scan partials
// Pre-packed B fragments for mma.sync m16n8k16 (row.col), hi/lo split of W.
__device__ uint2 g_bhi[8][16][32];
__device__ uint2 g_blo[8][16][32];

// ---------------------------------------------------------------------------
__device__ __forceinline__ int load_idx(const void* p, int e, int is64) {
    return is64 ? (int)((const long long*)p)[e] : ((const int*)p)[e];
}
__device__ __forceinline__ int detect_is64(const unsigned int* raw) {
    unsigned int acc = 0;
#pragma unroll
    for (int k = 0; k < 16; k++) acc |= raw[2 * k + 1];
    return (acc == 0u) ? 1 : 0;
}
__device__ __forceinline__ uint32_t pack_bf2(__nv_bfloat16 a, __nv_bfloat16 b) {
    __nv_bfloat162 p(a, b);
    return *(uint32_t*)&p;
}

// ---------------------------------------------------------------------------
// Kernel 0 (prep): pack W into hi/lo mma B-fragments; zero per-dst counters.
// ---------------------------------------------------------------------------
__global__ __launch_bounds__(256) void prep_kernel(const float* __restrict__ W)
{
    const int idx = blockIdx.x * 256 + threadIdx.x;
    if (idx < 8 * 16 * 32) {
        const int lane = idx & 31;
        const int nb   = (idx >> 5) & 15;
        const int kc   = idx >> 9;
        const int g = lane >> 2, t = lane & 3;
        const int n  = nb * 8 + g;
        const int k0 = kc * 16 + 2 * t;
        const float w0 = W[(k0    ) * DD + n];
        const float w1 = W[(k0 + 1) * DD + n];
        const float w2 = W[(k0 + 8) * DD + n];
        const float w3 = W[(k0 + 9) * DD + n];
        const __nv_bfloat16 h0 = __float2bfloat16(w0), h1 = __float2bfloat16(w1);
        const __nv_bfloat16 h2 = __float2bfloat16(w2), h3 = __float2bfloat16(w3);
        const __nv_bfloat16 l0 = __float2bfloat16(w0 - __bfloat162float(h0));
        const __nv_bfloat16 l1 = __float2bfloat16(w1 - __bfloat162float(h1));
        const __nv_bfloat16 l2 = __float2bfloat16(w2 - __bfloat162float(h2));
        const __nv_bfloat16 l3 = __float2bfloat16(w3 - __bfloat162float(h3));
        g_bhi[kc][nb][lane] = make_uint2(pack_bf2(h0, h1), pack_bf2(h2, h3));
        g_blo[kc][nb][lane] = make_uint2(pack_bf2(l0, l1), pack_bf2(l2, l3));
    }
    const int i = idx - 4096;
    if (i >= 0 && i < NN) g_cnt[i] = 0;
}

// ---------------------------------------------------------------------------
// Kernel 1: histogram of dst (self-detecting index dtype)
// ---------------------------------------------------------------------------
__global__ __launch_bounds__(256) void hist_kernel(const void* __restrict__ dst, int E)
{
    __shared__ int s_is64;
    if (threadIdx.x == 0) s_is64 = detect_is64((const unsigned int*)dst);
    __syncthreads();
    const int e = blockIdx.x * 256 + threadIdx.x;
    if (e >= E) return;
    const int d = load_idx(dst, e, s_is64);
    if ((unsigned)d < (unsigned)NN) atomicAdd(&g_cnt[d], 1);
}

// ---------------------------------------------------------------------------
// Kernel 2: scan1 (per-256-chunk sums)
// ---------------------------------------------------------------------------
__global__ __launch_bounds__(256) void scan1_kernel()
{
    __shared__ int sh[256];
    const int i = blockIdx.x * 256 + threadIdx.x;
    int v = (i < NN) ? g_cnt[i] : 0;
    sh[threadIdx.x] = v;
    __syncthreads();
#pragma unroll
    for (int s = 128; s > 0; s >>= 1) {
        if (threadIdx.x < s) sh[threadIdx.x] += sh[threadIdx.x + s];
        __syncthreads();
    }
    if (threadIdx.x == 0) g_chunksum[blockIdx.x] = sh[0];
}

// ---------------------------------------------------------------------------
// Kernel 3: m = H @ W via mma.sync bf16 hi/lo split (3 terms); fp16 output.
// 256 threads = 8 warps in 4(M)x2(N); block tile 128x128; warp tile 32x64.
// ---------------------------------------------------------------------------
#define ASTRIDE 72   // 64 + 8 pad (bf16 elems per smem row)

__device__ __forceinline__ void mma16816(float* c, const uint32_t* a, uint2 b) {
    asm volatile(
        "mma.sync.aligned.m16n8k16.row.col.f32.bf16.bf16.f32 "
        "{%0,%1,%2,%3}, {%4,%5,%6,%7}, {%8,%9}, {%0,%1,%2,%3};"
        : "+f"(c[0]), "+f"(c[1]), "+f"(c[2]), "+f"(c[3])
        : "r"(a[0]), "r"(a[1]), "r"(a[2]), "r"(a[3]), "r"(b.x), "r"(b.y));
}
__device__ __forceinline__ void ldmat4(uint32_t* f, uint32_t addr) {
    asm volatile("ldmatrix.sync.aligned.m8n8.x4.shared.b16 {%0,%1,%2,%3}, [%4];"
        : "=r"(f[0]), "=r"(f[1]), "=r"(f[2]), "=r"(f[3]) : "r"(addr));
}

__global__ __launch_bounds__(256, 2) void gemm_mma_kernel(const float* __restrict__ Hm)
{
    __shared__ __align__(16) __nv_bfloat16 Ahi[128][ASTRIDE];
    __shared__ __align__(16) __nv_bfloat16 Alo[128][ASTRIDE];

    const int tid = threadIdx.x;
    const int wid = tid >> 5, lane = tid & 31;
    const int wm = wid >> 1, wn = wid & 1;          // warp grid 4x2
    const int g = lane >> 2, t = lane & 3;
    const int rowBase = blockIdx.x * 128;

    float acc[2][8][4];
#pragma unroll
    for (int mb = 0; mb < 2; mb++)
#pragma unroll
        for (int j = 0; j < 8; j++)
#pragma unroll
            for (int c = 0; c < 4; c++) acc[mb][j][c] = 0.f;

    const uint32_t ahi_base = (uint32_t)__cvta_generic_to_shared(&Ahi[0][0]);
    const uint32_t alo_base = (uint32_t)__cvta_generic_to_shared(&Alo[0][0]);

    const int sub = lane >> 3, rr = lane & 7;
    const int lm_row_off = (sub & 1) * 8 + rr;      // 0..15
    const int lm_col_off = (sub >> 1) * 8;          // 0 or 8

    for (int kh = 0; kh < 2; kh++) {
        // Load H half-tile 128x64 fp32, convert to bf16 hi/lo in smem
#pragma unroll
        for (int q = 0; q < 8; q++) {
            const int idx = q * 256 + tid;          // 0..2047 float4 slots
            const int r  = idx >> 4;                // 16 float4 per row
            const int c4 = idx & 15;
            const int grow = rowBase + r;
            float4 v = make_float4(0.f, 0.f, 0.f, 0.f);
            if (grow < ROWS)
                v = *(const float4*)(Hm + (size_t)grow * DD + kh * 64 + c4 * 4);
            const __nv_bfloat16 h0 = __float2bfloat16(v.x), h1 = __float2bfloat16(v.y);
            const __nv_bfloat16 h2 = __float2bfloat16(v.z), h3 = __float2bfloat16(v.w);
            const __nv_bfloat16 l0 = __float2bfloat16(v.x - __bfloat162float(h0));
            const __nv_bfloat16 l1 = __float2bfloat16(v.y - __bfloat162float(h1));
            const __nv_bfloat16 l2 = __float2bfloat16(v.z - __bfloat162float(h2));
            const __nv_bfloat16 l3 = __float2bfloat16(v.w - __bfloat162float(h3));
            *(uint2*)&Ahi[r][c4 * 4] = make_uint2(pack_bf2(h0, h1), pack_bf2(h2, h3));
            *(uint2*)&Alo[r][c4 * 4] = make_uint2(pack_bf2(l0, l1), pack_bf2(l2, l3));
        }
        __syncthreads();

#pragma unroll
        for (int kc = 0; kc < 4; kc++) {
            uint32_t ah[2][4], al[2][4];
#pragma unroll
            for (int mb = 0; mb < 2; mb++) {
                const int row = wm * 32 + mb * 16 + lm_row_off;
                const int col = kc * 16 + lm_col_off;
                const uint32_t boff = (uint32_t)(row * ASTRIDE + col) * 2u;
                ldmat4(ah[mb], ahi_base + boff);
                ldmat4(al[mb], alo_base + boff);
            }
            const int kcg = kh * 4 + kc;
#pragma unroll
            for (int j = 0; j < 8; j++) {
                const int nb = wn * 8 + j;
                const uint2 bh = g_bhi[kcg][nb][lane];
                const uint2 bl = g_blo[kcg][nb][lane];
#pragma unroll
                for (int mb = 0; mb < 2; mb++) {
                    mma16816(acc[mb][j], ah[mb], bh);
                    mma16816(acc[mb][j], ah[mb], bl);
                    mma16816(acc[mb][j], al[mb], bh);
                }
            }
        }
        __syncthreads();
    }

    // Epilogue: write D fragments as fp16 (half2 per 2-col group)
#pragma unroll
    for (int mb = 0; mb < 2; mb++) {
        const int row0 = rowBase + wm * 32 + mb * 16 + g;
        const int row1 = row0 + 8;
#pragma unroll
        for (int j = 0; j < 8; j++) {
            const int col = wn * 64 + j * 8 + 2 * t;
            if (row0 < ROWS)
                *(__half2*)(g_m + (size_t)row0 * DD + col) =
                    __floats2half2_rn(acc[mb][j][0], acc[mb][j][1]);
            if (row1 < ROWS)
                *(__half2*)(g_m + (size_t)row1 * DD + col) =
                    __floats2half2_rn(acc[mb][j][2], acc[mb][j][3]);
        }
    }
}

// ---------------------------------------------------------------------------
// Kernel 4: scan2 (exclusive scan of chunk sums)
// ---------------------------------------------------------------------------
__global__ __launch_bounds__(256) void scan2_kernel()
{
    __shared__ int sh[256];
    const int t = threadIdx.x;
    int v = (t < NCHUNK) ? g_chunksum[t] : 0;
    sh[t] = v;
    __syncthreads();
#pragma unroll
    for (int o = 1; o < 256; o <<= 1) {
        int add = (t >= o) ? sh[t - o] : 0;
        __syncthreads();
        sh[t] += add;
        __syncthreads();
    }
    if (t < NCHUNK) g_chunksum[t] = sh[t] - v;   // exclusive
}

// ---------------------------------------------------------------------------
// Kernel 5: scan3 (per-element offsets)
// ---------------------------------------------------------------------------
__global__ __launch_bounds__(256) void scan3_kernel()
{
    __shared__ int sh[256];
    const int t = threadIdx.x;
    const int i = blockIdx.x * 256 + t;
    int v = (i < NN) ? g_cnt[i] : 0;
    sh[t] = v;
    __syncthreads();
#pragma unroll
    for (int o = 1; o < 256; o <<= 1) {
        int add = (t >= o) ? sh[t - o] : 0;
        __syncthreads();
        sh[t] += add;
        __syncthreads();
    }
    if (i < NN) {
        const int off = g_chunksum[blockIdx.x] + sh[t] - v;   // exclusive
        g_off[i] = off;
        g_cur[i] = off;
        if (i == NN - 1) g_off[NN] = off + v;
    }
}

// ---------------------------------------------------------------------------
// Kernel 6: fill CSR (src grouped by dst)
// ---------------------------------------------------------------------------
__global__ __launch_bounds__(256) void fill_kernel(
    const void* __restrict__ src, const void* __restrict__ dst, int E)
{
    __shared__ int s_is64;
    if (threadIdx.x == 0) s_is64 = detect_is64((const unsigned int*)dst);
    __syncthreads();
    const int e = blockIdx.x * 256 + threadIdx.x;
    if (e >= E) return;
    const int d = load_idx(dst, e, s_is64);
    const int s = load_idx(src, e, s_is64);
    if ((unsigned)d >= (unsigned)NN || (unsigned)s >= (unsigned)NN) return;
    const int pos = atomicAdd(&g_cur[d], 1);
    if (pos < EMAX) g_esrc[pos] = s;
}

// ---------------------------------------------------------------------------
// Kernel 7: fused gather-accumulate (fp16 m) + residual + GELU + LayerNorm.
// One warp per (b,row); lane covers 4 contiguous halves (uint2 = 8 bytes).
// ---------------------------------------------------------------------------
__device__ __forceinline__ float gelu_exact(float x) {
    return 0.5f * x * (1.0f + erff(x * 0.70710678118654752f));
}

__global__ __launch_bounds__(256) void agg_ln_kernel(
    const float* __restrict__ Hm, const float* __restrict__ gamma,
    const float* __restrict__ beta, float* __restrict__ out)
{
    const int gw = blockIdx.x * 8 + (threadIdx.x >> 5);
    if (gw >= 2 * NN) return;
    const int lane = threadIdx.x & 31;
    const int b   = (gw >= NN) ? 1 : 0;
    const int row = gw - b * NN;

    const int beg = g_off[row];
    const int end = g_off[row + 1];

    float4 a0 = make_float4(0.f, 0.f, 0.f, 0.f);
    float4 a1 = make_float4(0.f, 0.f, 0.f, 0.f);

    // m rows: 128 halves = 32 uint2 per row; lane loads halves [4*lane, 4*lane+4)
    const uint2* mb = (const uint2*)(g_m + (size_t)b * NN * DD);
    int i = beg;
    for (; i + 1 < end; i += 2) {
        const int s0 = g_esrc[i];
        const int s1 = g_esrc[i + 1];
        const uint2 v0 = mb[(size_t)s0 * 32 + lane];
        const uint2 v1 = mb[(size_t)s1 * 32 + lane];
        const float2 f00 = __half22float2(*(const __half2*)&v0.x);
        const float2 f01 = __half22float2(*(const __half2*)&v0.y);
        const float2 f10 = __half22float2(*(const __half2*)&v1.x);
        const float2 f11 = __half22float2(*(const __half2*)&v1.y);
        a0.x += f00.x; a0.y += f00.y; a0.z += f01.x; a0.w += f01.y;
        a1.x += f10.x; a1.y += f10.y; a1.z += f11.x; a1.w += f11.y;
    }
    if (i < end) {
        const int s0 = g_esrc[i];
        const uint2 v0 = mb[(size_t)s0 * 32 + lane];
        const float2 f00 = __half22float2(*(const __half2*)&v0.x);
        const float2 f01 = __half22float2(*(const __half2*)&v0.y);
        a0.x += f00.x; a0.y += f00.y; a0.z += f01.x; a0.w += f01.y;
    }
    a0.x += a1.x; a0.y += a1.y; a0.z += a1.z; a0.w += a1.w;

    const size_t rq = (size_t)(b * NN + row) * 32 + lane;
    const float4 h = ((const float4*)Hm)[rq];

    float4 x;
    x.x = h.x + gelu_exact(a0.x);
    x.y = h.y + gelu_exact(a0.y);
    x.z = h.z + gelu_exact(a0.z);
    x.w = h.w + gelu_exact(a0.w);

    float s  = x.x + x.y + x.z + x.w;
    float ss = fmaf(x.x, x.x, fmaf(x.y, x.y, fmaf(x.z, x.z, x.w * x.w)));
#pragma unroll
    for (int o = 16; o > 0; o >>= 1) {
        s  += __shfl_xor_sync(0xFFFFFFFFu, s,  o);
        ss += __shfl_xor_sync(0xFFFFFFFFu, ss, o);
    }
    const float mean = s * (1.0f / 128.0f);
    const float var  = ss * (1.0f / 128.0f) - mean * mean;
    const float rstd = rsqrtf(var + 1e-5f);

    const float4 g  = ((const float4*)gamma)[lane];
    const float4 bt = ((const float4*)beta)[lane];

    float4 o4;
    o4.x = (x.x - mean) * rstd * g.x + bt.x;
    o4.y = (x.y - mean) * rstd * g.y + bt.y;
    o4.z = (x.z - mean) * rstd * g.z + bt.z;
    o4.w = (x.w - mean) * rstd * g.w + bt.w;

    ((float4*)out)[rq] = o4;
}

// ---------------------------------------------------------------------------
extern "C" void kernel_launch(void* const* d_in, const int* in_sizes, int n_in,
                              void* d_out, int out_size)
{
    const float* H     = (const float*)d_in[0];
    const void*  src   = d_in[1];
    const void*  dst   = d_in[2];
    const float* W     = (const float*)d_in[3];
    const float* gamma = (const float*)d_in[4];
    const float* beta  = (const float*)d_in[5];
    const int E = in_sizes[1];
    const int eb = (E + 255) / 256;

    // Side stream + events, created once on the first (uncaptured) call.
    static cudaStream_t s_side = 0;
    static cudaEvent_t  ev_fork = 0, ev_join = 0;
    if (s_side == 0) {
        cudaStreamCreateWithFlags(&s_side, cudaStreamNonBlocking);
        cudaEventCreateWithFlags(&ev_fork, cudaEventDisableTiming);
        cudaEventCreateWithFlags(&ev_join, cudaEventDisableTiming);
    }

    // 1) prep: pack W fragments (hi/lo) + zero counters  (main stream)
    prep_kernel<<<(4096 + NN + 255) / 256, 256>>>(W);

    // Fork: GEMM on side stream, CSR build on main stream (independent data)
    cudaEventRecord(ev_fork, 0);
    cudaStreamWaitEvent(s_side, ev_fork, 0);

    gemm_mma_kernel<<<(ROWS + 127) / 128, 256, 0, s_side>>>(H);

    hist_kernel<<<eb, 256>>>(dst, E);
    scan1_kernel<<<NCHUNK, 256>>>();
    scan2_kernel<<<1, 256>>>();
    scan3_kernel<<<NCHUNK, 256>>>();
    fill_kernel<<<eb, 256>>>(src, dst, E);

    // Join: agg_ln needs both g_m (side) and CSR (main)
    cudaEventRecord(ev_join, s_side);
    cudaStreamWaitEvent(0, ev_join, 0);

    // 2) fused gather + residual + GELU + LayerNorm
    agg_ln_kernel<<<(2 * NN + 7) / 8, 256>>>(H, gamma, beta, (float*)d_out);
}